// round 7
// baseline (speedup 1.0000x reference)
#include <cuda_runtime.h>
#include <math.h>

// ---------------- scratch (device globals; no allocations allowed) -------------
#define BATCH 16
__device__ float  g_stem_out[BATCH*64*256*256];   // conv-stem output (NCHW)
__device__ float  g_f[BATCH*64*128*128];          // f after BN+relu+maxpool
__device__ float  g_xt[2*BATCH*64*128*128];       // grid-sampled xt1, xt2
__device__ float  g_h[BATCH*704*529];             // concat roialign features
__device__ float  g_c1[BATCH*64*441];             // conv1 output (21x21)
__device__ float  g_p1[BATCH*64*100];             // after bn1+relu+pool (10x10)
__device__ float  g_fcin[BATCH*2048];             // conv2+relu, flattened
__device__ float  g_fc1v[BATCH*128];              // fc1+relu
__device__ double g_ssum[64];
__device__ double g_ssq[64];
__device__ float  g_sscale[64], g_sshift[64];
__device__ float  g_b1scale[64], g_b1shift[64];

// ---------------- zero accumulators (needed every graph replay) ----------------
__global__ void k_zero() {
    int idx = blockIdx.x * 256 + threadIdx.x;
    if (idx < 64) { g_ssum[idx] = 0.0; g_ssq[idx] = 0.0; }
    for (int i = idx; i < BATCH*64*441; i += gridDim.x * 256) g_c1[i] = 0.0f;
}

// ---------------- stem conv: 7x7 s2 p3, NHWC in -> NCHW out --------------------
// block: 256 thr; tile = 16 oc x 8 rows x 32 cols; thread = 4 oc x 4 cols.
__global__ __launch_bounds__(256) void k_stem_conv(const float* __restrict__ x,
                                                   const float* __restrict__ w) {
    __shared__ float s_in[3*21*72];   // [c][21][72], 69 cols used
    __shared__ float s_w[2352];       // [(c*7+kh)*7+kw][16 oc]
    const int tid = threadIdx.x;
    const int b   = blockIdx.z >> 2;
    const int oc0 = (blockIdx.z & 3) * 16;
    const int base_ih = blockIdx.y * 16 - 3;
    const int base_iw = blockIdx.x * 64 - 3;

    for (int i = tid; i < 3*21*69; i += 256) {
        int c = i % 3, t = i / 3, ww = t % 69, hh = t / 69;
        int ih = base_ih + hh, iw = base_iw + ww;
        float v = 0.0f;
        if ((unsigned)ih < 512u && (unsigned)iw < 512u)
            v = x[((b*512 + ih)*512 + iw)*3 + c];
        s_in[(c*21 + hh)*72 + ww] = v;
    }
    for (int i = tid; i < 2352; i += 256) {
        int oc = i & 15, r = i >> 4;
        s_w[i] = w[(oc0 + oc)*147 + r];
    }
    __syncthreads();

    const int gx = tid & 7, gy = (tid >> 3) & 7, og = tid >> 6;
    float acc[4][4];
#pragma unroll
    for (int o = 0; o < 4; o++)
#pragma unroll
        for (int j = 0; j < 4; j++) acc[o][j] = 0.0f;

#pragma unroll
    for (int c = 0; c < 3; c++)
#pragma unroll
    for (int kh = 0; kh < 7; kh++) {
        const float* rp = &s_in[(c*21 + gy*2 + kh)*72 + gx*8];
        float4 a0 = *(const float4*)(rp);
        float4 a1 = *(const float4*)(rp + 4);
        float4 a2 = *(const float4*)(rp + 8);
        float in13[13] = {a0.x,a0.y,a0.z,a0.w, a1.x,a1.y,a1.z,a1.w,
                          a2.x,a2.y,a2.z,a2.w, rp[12]};
        const float* wp = &s_w[((c*7 + kh)*7)*16 + og*4];
#pragma unroll
        for (int kw = 0; kw < 7; kw++) {
            float4 wv = *(const float4*)(wp + kw*16);
#pragma unroll
            for (int j = 0; j < 4; j++) {
                float v = in13[kw + 2*j];
                acc[0][j] = fmaf(wv.x, v, acc[0][j]);
                acc[1][j] = fmaf(wv.y, v, acc[1][j]);
                acc[2][j] = fmaf(wv.z, v, acc[2][j]);
                acc[3][j] = fmaf(wv.w, v, acc[3][j]);
            }
        }
    }
    const int oh  = blockIdx.y*8 + gy;
    const int ow0 = blockIdx.x*32 + gx*4;
#pragma unroll
    for (int o = 0; o < 4; o++) {
        int base = ((b*64 + oc0 + og*4 + o)*256 + oh)*256 + ow0;
        float4 st = make_float4(acc[o][0], acc[o][1], acc[o][2], acc[o][3]);
        *(float4*)&g_stem_out[base] = st;
    }
}

// ---------------- stem BN stats -----------------------------------------------
__global__ void k_stem_stats() {
    const int c = blockIdx.x, b = blockIdx.y;
    const float* p = g_stem_out + (size_t)(b*64 + c)*65536;
    float s = 0.0f, q = 0.0f;
    for (int i = threadIdx.x; i < 65536; i += 256) {
        float v = p[i]; s += v; q += v*v;
    }
#pragma unroll
    for (int off = 16; off; off >>= 1) {
        s += __shfl_down_sync(0xffffffffu, s, off);
        q += __shfl_down_sync(0xffffffffu, q, off);
    }
    __shared__ float w1[8], w2[8];
    int lane = threadIdx.x & 31, wid = threadIdx.x >> 5;
    if (lane == 0) { w1[wid] = s; w2[wid] = q; }
    __syncthreads();
    if (threadIdx.x == 0) {
        float ts = 0.0f, tq = 0.0f;
        for (int i = 0; i < 8; i++) { ts += w1[i]; tq += w2[i]; }
        atomicAdd(&g_ssum[c], (double)ts);
        atomicAdd(&g_ssq[c],  (double)tq);
    }
}

__global__ void k_stem_prepare(const float* __restrict__ g,
                               const float* __restrict__ bb) {
    int c = threadIdx.x;
    double N = 1048576.0;
    double mean = g_ssum[c] / N;
    double var  = g_ssq[c] / N - mean*mean;
    float sc = g[c] * rsqrtf((float)var + 1e-5f);
    g_sscale[c] = sc;
    g_sshift[c] = bb[c] - (float)mean * sc;
}

// ---------------- BN apply + relu + maxpool 3x3 s2 p1 -> f ---------------------
__global__ void k_stem_pool() {
    __shared__ float s[17*66];
    const int z = blockIdx.z;           // b*64 + c
    const float sc = g_sscale[z & 63], sh = g_sshift[z & 63];
    const float* p = g_stem_out + (size_t)z*65536;
    const int y0 = blockIdx.y*8, x0 = blockIdx.x*32;
    const int ihb = 2*y0 - 1, iwb = 2*x0 - 1;
    for (int i = threadIdx.x; i < 17*65; i += 256) {
        int r = i / 65, cc = i % 65;
        int ih = ihb + r, iw = iwb + cc;
        float v = 0.0f;
        if ((unsigned)ih < 256u && (unsigned)iw < 256u)
            v = fmaxf(fmaf(p[ih*256 + iw], sc, sh), 0.0f);
        s[r*66 + cc] = v;
    }
    __syncthreads();
    int tx = threadIdx.x & 31, ty = threadIdx.x >> 5;
    float m = 0.0f;
#pragma unroll
    for (int dr = 0; dr < 3; dr++)
#pragma unroll
        for (int dc = 0; dc < 3; dc++)
            m = fmaxf(m, s[(2*ty + dr)*66 + 2*tx + dc]);
    g_f[(size_t)z*16384 + (y0 + ty)*128 + x0 + tx] = m;
}

// ---------------- grid_sample (±5° rotation) -> xt1/xt2 ------------------------
__device__ __forceinline__ float gs_tap(const float* p, float yy, float xx) {
    bool v = (xx >= 0.0f) && (xx < 128.0f) && (yy >= 0.0f) && (yy < 128.0f);
    int xi = (int)fminf(fmaxf(xx, 0.0f), 127.0f);
    int yi = (int)fminf(fmaxf(yy, 0.0f), 127.0f);
    return v ? p[yi*128 + xi] : 0.0f;
}

__global__ void k_gridsample() {
    const int z = blockIdx.z;
    const int t = z >> 10;              // 0: theta1, 1: theta2
    const int bc = z & 1023;            // b*64 + c
    const int x = blockIdx.x*32 + (threadIdx.x & 31);
    const int y = blockIdx.y*8  + (threadIdx.x >> 5);
    const float C0 = 0.99619469809174553f;
    const float S5 = 0.08715574274765817f;
    float gx = (2*x + 1)*(1.0f/128.0f) - 1.0f;
    float gy = (2*y + 1)*(1.0f/128.0f) - 1.0f;
    float sg = t ? -S5 : S5;
    float gxp =  C0*gx + sg*gy;
    float gyp = -sg*gx + C0*gy;
    float ix = ((gxp + 1.0f)*128.0f - 1.0f)*0.5f;
    float iy = ((gyp + 1.0f)*128.0f - 1.0f)*0.5f;
    float x0f = floorf(ix), y0f = floorf(iy);
    float lx = ix - x0f, ly = iy - y0f;
    const float* p = g_f + (size_t)bc*16384;
    float r = gs_tap(p, y0f,        x0f)        * (1.0f - lx)*(1.0f - ly)
            + gs_tap(p, y0f + 1.0f, x0f)        * (1.0f - lx)*ly
            + gs_tap(p, y0f,        x0f + 1.0f) * lx*(1.0f - ly)
            + gs_tap(p, y0f + 1.0f, x0f + 1.0f) * lx*ly;
    g_xt[(size_t)t*16777216 + (size_t)bc*16384 + y*128 + x] = r;
}

// ---------------- roialign -> h (16, 704, 23, 23) ------------------------------
__global__ void k_roialign(const float* __restrict__ box) {
    int idx = blockIdx.x*256 + threadIdx.x;
    if (idx >= 64*529) return;
    const int c  = idx / 529;
    const int sp = idx % 529;
    const int ph = sp / 23, pw = sp % 23;
    const int combo = blockIdx.y, b = blockIdx.z;

    const float* src; int slot, choff;
    if (combo < 7) { src = g_f; slot = combo; choff = combo*64; }
    else {
        int k2 = combo - 7;
        src = g_xt + (size_t)(k2 >> 1)*16777216;
        slot = k2 & 1; choff = 448 + k2*64;
    }
    const float* bp = box + b*28 + slot*4;
    float x1 = bp[0]*0.25f, y1 = bp[1]*0.25f;
    float x2 = bp[2]*0.25f, y2 = bp[3]*0.25f;
    float bw = fmaxf(x2 - x1, 1.0f) / 23.0f;
    float bh = fmaxf(y2 - y1, 1.0f) / 23.0f;
    const float* p = src + (size_t)(b*64 + c)*16384;

    float acc = 0.0f;
#pragma unroll
    for (int oi = 0; oi < 2; oi++)
#pragma unroll
    for (int oj = 0; oj < 2; oj++) {
        float py = (float)ph + (oi*0.5f + 0.25f);
        float px = (float)pw + (oj*0.5f + 0.25f);
        float yv = y1 + py*bh;
        float xv = x1 + px*bw;
        bool empty = (yv < -1.0f) || (yv > 128.0f) || (xv < -1.0f) || (xv > 128.0f);
        float yc = fminf(fmaxf(yv, 0.0f), 127.0f);
        float xc = fminf(fmaxf(xv, 0.0f), 127.0f);
        float y0f = floorf(yc), x0f = floorf(xc);
        int yi = (int)y0f, xi = (int)x0f;
        int yi1 = min(yi + 1, 127), xi1 = min(xi + 1, 127);
        float ly = yc - y0f, lx = xc - x0f;
        float hy = 1.0f - ly, hx = 1.0f - lx;
        float v = p[yi*128  + xi ] * hy*hx + p[yi*128  + xi1] * hy*lx
                + p[yi1*128 + xi ] * ly*hx + p[yi1*128 + xi1] * ly*lx;
        acc += empty ? 0.0f : v;
    }
    g_h[((size_t)(b*704 + choff + c))*529 + sp] = acc * 0.25f;
}

// ---------------- conv1: 3x3 p0, 704->64, 23x23 -> 21x21 -----------------------
// grid (2 cin-splits, 8 oc-groups, 16 b); block 448 thr (441 active spatial)
__global__ __launch_bounds__(448) void k_conv1(const float* __restrict__ w) {
    __shared__ float s_in[4416];   // [8][23][24]
    __shared__ float s_w[576];     // [(c8*9+kh*3+kw)][8 oc]
    const int tid = threadIdx.x;
    const int split = blockIdx.x, ocg = blockIdx.y, b = blockIdx.z;
    const int oc0 = ocg*8;
    const int y = tid / 21, x = tid % 21;
    const bool act = tid < 441;
    float acc[8];
#pragma unroll
    for (int o = 0; o < 8; o++) acc[o] = 0.0f;

    for (int cc = split*352; cc < split*352 + 352; cc += 8) {
        __syncthreads();
        for (int i = tid; i < 8*529; i += 448) {
            int c8 = i / 529, r = i % 529;
            s_in[(c8*23 + r/23)*24 + r%23] = g_h[((size_t)(b*704 + cc + c8))*529 + r];
        }
        for (int i = tid; i < 576; i += 448) {
            int oc = i & 7, r = i >> 3;
            s_w[i] = w[(oc0 + oc)*6336 + (cc + r/9)*9 + r%9];
        }
        __syncthreads();
        if (act) {
#pragma unroll
            for (int c8 = 0; c8 < 8; c8++) {
#pragma unroll
                for (int kh = 0; kh < 3; kh++) {
                    const float* rp = &s_in[(c8*23 + y + kh)*24 + x];
                    float v0 = rp[0], v1 = rp[1], v2 = rp[2];
                    const float* wp = &s_w[(c8*9 + kh*3)*8];
#pragma unroll
                    for (int kw = 0; kw < 3; kw++) {
                        float v = (kw == 0) ? v0 : (kw == 1) ? v1 : v2;
                        float4 wa = *(const float4*)(wp + kw*8);
                        float4 wb = *(const float4*)(wp + kw*8 + 4);
                        acc[0] = fmaf(wa.x, v, acc[0]); acc[1] = fmaf(wa.y, v, acc[1]);
                        acc[2] = fmaf(wa.z, v, acc[2]); acc[3] = fmaf(wa.w, v, acc[3]);
                        acc[4] = fmaf(wb.x, v, acc[4]); acc[5] = fmaf(wb.y, v, acc[5]);
                        acc[6] = fmaf(wb.z, v, acc[6]); acc[7] = fmaf(wb.w, v, acc[7]);
                    }
                }
            }
        }
    }
    if (act) {
#pragma unroll
        for (int o = 0; o < 8; o++)
            atomicAdd(&g_c1[((size_t)(b*64 + oc0 + o))*441 + tid], acc[o]);
    }
}

// ---------------- bn1 stats (conv1_b cancels inside BN; skipped) ---------------
__global__ void k_bn1stats(const float* __restrict__ g, const float* __restrict__ bb) {
    const int c = blockIdx.x;
    float s = 0.0f, q = 0.0f;
    for (int i = threadIdx.x; i < 7056; i += 256) {
        int b = i / 441, sp = i % 441;
        float v = g_c1[((size_t)(b*64 + c))*441 + sp];
        s += v; q += v*v;
    }
#pragma unroll
    for (int off = 16; off; off >>= 1) {
        s += __shfl_down_sync(0xffffffffu, s, off);
        q += __shfl_down_sync(0xffffffffu, q, off);
    }
    __shared__ float w1[8], w2[8];
    int lane = threadIdx.x & 31, wid = threadIdx.x >> 5;
    if (lane == 0) { w1[wid] = s; w2[wid] = q; }
    __syncthreads();
    if (threadIdx.x == 0) {
        float ts = 0.0f, tq = 0.0f;
        for (int i = 0; i < 8; i++) { ts += w1[i]; tq += w2[i]; }
        float mean = ts / 7056.0f;
        float var  = tq / 7056.0f - mean*mean;
        float sc = g[c] * rsqrtf(var + 1e-5f);
        g_b1scale[c] = sc;
        g_b1shift[c] = bb[c] - mean*sc;
    }
}

// ---------------- bn1 apply + relu + maxpool 2x2 s2 ----------------------------
__global__ void k_pool2() {
    int idx = blockIdx.x*256 + threadIdx.x;
    if (idx >= BATCH*64*100) return;
    int b = idx / 6400, r = idx % 6400;
    int c = r / 100, sxy = r % 100;
    int y = sxy / 10, x = sxy % 10;
    float sc = g_b1scale[c], sh = g_b1shift[c];
    const float* p = g_c1 + (size_t)(b*64 + c)*441;
    float m = -1e30f;
#pragma unroll
    for (int dr = 0; dr < 2; dr++)
#pragma unroll
        for (int dc = 0; dc < 2; dc++) {
            float v = fmaxf(fmaf(p[(2*y + dr)*21 + 2*x + dc], sc, sh), 0.0f);
            m = fmaxf(m, v);
        }
    g_p1[idx] = m;
}

// ---------------- conv2: 3x3 p0, 64->32, 10x10 -> 8x8, +bias, relu ------------
__global__ void k_conv2(const float* __restrict__ w, const float* __restrict__ bias) {
    __shared__ float s_in[3200];   // [32][10][10]
    __shared__ float s_w[2304];    // [(c*9+t)][8 oc]
    const int tid = threadIdx.x;
    const int ocg = blockIdx.x, b = blockIdx.y;
    const int oc0 = ocg*8;
    const int s = tid & 63, og = tid >> 6;
    const int y = s >> 3, x = s & 7;
    float acc[2] = {0.0f, 0.0f};

    for (int cc = 0; cc < 64; cc += 32) {
        __syncthreads();
        for (int i = tid; i < 3200; i += 256)
            s_in[i] = g_p1[((size_t)(b*64 + cc))*100 + i];
        for (int i = tid; i < 2304; i += 256) {
            int oc = i & 7, r = i >> 3;
            s_w[i] = w[(oc0 + oc)*576 + (cc + r/9)*9 + r%9];
        }
        __syncthreads();
#pragma unroll 4
        for (int c = 0; c < 32; c++) {
#pragma unroll
            for (int kh = 0; kh < 3; kh++) {
                const float* rp = &s_in[(c*10 + y + kh)*10 + x];
                float v0 = rp[0], v1 = rp[1], v2 = rp[2];
                const float* wp = &s_w[(c*9 + kh*3)*8 + og*2];
                acc[0] = fmaf(wp[0],  v0, acc[0]); acc[1] = fmaf(wp[1],  v0, acc[1]);
                acc[0] = fmaf(wp[8],  v1, acc[0]); acc[1] = fmaf(wp[9],  v1, acc[1]);
                acc[0] = fmaf(wp[16], v2, acc[0]); acc[1] = fmaf(wp[17], v2, acc[1]);
            }
        }
    }
#pragma unroll
    for (int o = 0; o < 2; o++) {
        int oc = oc0 + og*2 + o;
        g_fcin[b*2048 + oc*64 + s] = fmaxf(acc[o] + bias[oc], 0.0f);
    }
}

// ---------------- fc1: (16,2048) x (128,2048)^T + b, relu ----------------------
__global__ void k_fc1(const float* __restrict__ w, const float* __restrict__ bias) {
    const int j = blockIdx.x;
    float acc[16];
#pragma unroll
    for (int b = 0; b < 16; b++) acc[b] = 0.0f;
    for (int k = threadIdx.x; k < 2048; k += 256) {
        float wv = w[j*2048 + k];
#pragma unroll
        for (int b = 0; b < 16; b++)
            acc[b] = fmaf(wv, g_fcin[b*2048 + k], acc[b]);
    }
#pragma unroll
    for (int off = 16; off; off >>= 1)
#pragma unroll
        for (int b = 0; b < 16; b++)
            acc[b] += __shfl_down_sync(0xffffffffu, acc[b], off);
    __shared__ float red[8][16];
    int lane = threadIdx.x & 31, wid = threadIdx.x >> 5;
    if (lane == 0)
#pragma unroll
        for (int b = 0; b < 16; b++) red[wid][b] = acc[b];
    __syncthreads();
    if (threadIdx.x < 16) {
        float sv = 0.0f;
        for (int wdx = 0; wdx < 8; wdx++) sv += red[wdx][threadIdx.x];
        g_fc1v[threadIdx.x*128 + j] = fmaxf(sv + bias[j], 0.0f);
    }
}

// ---------------- head + tanh --------------------------------------------------
__global__ void k_head(const float* __restrict__ w, const float* __restrict__ bias,
                       float* __restrict__ out) {
    int t = threadIdx.x;          // 192 threads
    int b = t / 12, j = t % 12;
    float s = bias[j];
    for (int k = 0; k < 128; k++)
        s = fmaf(g_fc1v[b*128 + k], w[j*128 + k], s);
    out[t] = tanhf(s);
}

// ---------------- launch -------------------------------------------------------
extern "C" void kernel_launch(void* const* d_in, const int* in_sizes, int n_in,
                              void* d_out, int out_size) {
    const float* x       = (const float*)d_in[0];
    const float* box     = (const float*)d_in[1];
    const float* stem_w  = (const float*)d_in[2];
    const float* stem_g  = (const float*)d_in[3];
    const float* stem_b  = (const float*)d_in[4];
    const float* conv1_w = (const float*)d_in[5];
    /* conv1_b (d_in[6]) cancels exactly inside batchnorm — unused */
    const float* bn1_g   = (const float*)d_in[7];
    const float* bn1_b   = (const float*)d_in[8];
    const float* conv2_w = (const float*)d_in[9];
    const float* conv2_b = (const float*)d_in[10];
    const float* fc1_w   = (const float*)d_in[11];
    const float* fc1_b   = (const float*)d_in[12];
    const float* head_w  = (const float*)d_in[13];
    const float* head_b  = (const float*)d_in[14];
    float* out = (float*)d_out;

    k_zero<<<512, 256>>>();
    k_stem_conv<<<dim3(8, 32, 64), 256>>>(x, stem_w);
    k_stem_stats<<<dim3(64, 16), 256>>>();
    k_stem_prepare<<<1, 64>>>(stem_g, stem_b);
    k_stem_pool<<<dim3(4, 16, 1024), 256>>>();
    k_gridsample<<<dim3(4, 16, 2048), 256>>>();
    k_roialign<<<dim3(133, 11, 16), 256>>>(box);
    k_conv1<<<dim3(2, 8, 16), 448>>>(conv1_w);
    k_bn1stats<<<64, 256>>>(bn1_g, bn1_b);
    k_pool2<<<400, 256>>>();
    k_conv2<<<dim3(4, 16), 256>>>(conv2_w, conv2_b);
    k_fc1<<<128, 256>>>(fc1_w, fc1_b);
    k_head<<<1, 192>>>(head_w, head_b, out);
}

// round 8
// speedup vs baseline: 1.0046x; 1.0046x over previous
#include <cuda_runtime.h>
#include <math.h>

// ---------------- scratch (device globals; no allocations allowed) -------------
#define BATCH 16
__device__ float  g_stem_out[BATCH*64*256*256];   // conv-stem output (NCHW)
__device__ float  g_f[BATCH*64*128*128];          // f after BN+relu+maxpool
__device__ float  g_xt[2*BATCH*64*128*128];       // grid-sampled xt1, xt2
__device__ float  g_h[BATCH*704*529];             // concat roialign features
__device__ float  g_c1[BATCH*64*441];             // conv1 output (21x21)
__device__ float  g_p1[BATCH*64*100];             // after bn1+relu+pool (10x10)
__device__ float  g_fcin[BATCH*2048];             // conv2+relu, flattened
__device__ float  g_fc1v[BATCH*128];              // fc1+relu
__device__ double g_psum[64*16];                  // per (c,b) partial BN sums
__device__ double g_psq [64*16];
__device__ float  g_sscale[64], g_sshift[64];
__device__ float  g_b1scale[64], g_b1shift[64];

// ---------------- packed f32x2 helpers -----------------------------------------
typedef unsigned long long u64;
__device__ __forceinline__ u64 pack2(float lo, float hi) {
    u64 r; asm("mov.b64 %0,{%1,%2};" : "=l"(r) : "f"(lo), "f"(hi)); return r;
}
__device__ __forceinline__ void ffma2(u64& d, u64 a, u64 b) {
    asm("fma.rn.f32x2 %0,%1,%2,%0;" : "+l"(d) : "l"(a), "l"(b));
}
__device__ __forceinline__ float2 unpack2(u64 v) {
    float2 r; asm("mov.b64 {%0,%1},%2;" : "=f"(r.x), "=f"(r.y) : "l"(v)); return r;
}

// ---------------- zero accumulators (needed every graph replay) ----------------
__global__ void k_zero() {
    int idx = blockIdx.x * 256 + threadIdx.x;
    if (idx < 1024) { g_psum[idx] = 0.0; g_psq[idx] = 0.0; }
    for (int i = idx; i < BATCH*64*441; i += gridDim.x * 256) g_c1[i] = 0.0f;
}

// ---------------- stem conv: 7x7 s2 p3, NHWC in -> NCHW out --------------------
// block: 256 thr; tile = 16 oc x 8 rows x 32 cols; thread = 4 oc x 4 cols.
// FFMA2 over oc-pairs; fused per-block BN partial stats.
__global__ __launch_bounds__(256) void k_stem_conv(const float* __restrict__ x,
                                                   const float* __restrict__ w) {
    __shared__ float s_in[3*21*72];   // [c][21][72], 69 cols used
    __shared__ float s_w[2352];       // [(c*7+kh)*7+kw][16 oc]
    __shared__ float s_red[8][8];     // per-warp stats partials
    const int tid = threadIdx.x;
    const int b   = blockIdx.z >> 2;
    const int oc0 = (blockIdx.z & 3) * 16;
    const int base_ih = blockIdx.y * 16 - 3;
    const int base_iw = blockIdx.x * 64 - 3;

    for (int i = tid; i < 3*21*69; i += 256) {
        int c = i % 3, t = i / 3, ww = t % 69, hh = t / 69;
        int ih = base_ih + hh, iw = base_iw + ww;
        float v = 0.0f;
        if ((unsigned)ih < 512u && (unsigned)iw < 512u)
            v = x[((b*512 + ih)*512 + iw)*3 + c];
        s_in[(c*21 + hh)*72 + ww] = v;
    }
    for (int i = tid; i < 2352; i += 256) {
        int oc = i & 15, r = i >> 4;
        s_w[i] = w[(oc0 + oc)*147 + r];
    }
    __syncthreads();

    const int gx = tid & 7, gy = (tid >> 3) & 7, og = tid >> 6;
    // acc2[p][j]: packed fp32x2 over oc pair (og*4+2p, og*4+2p+1), output col j
    u64 acc2[2][4];
#pragma unroll
    for (int p = 0; p < 2; p++)
#pragma unroll
        for (int j = 0; j < 4; j++) acc2[p][j] = 0ull;

#pragma unroll
    for (int c = 0; c < 3; c++)
#pragma unroll
    for (int kh = 0; kh < 7; kh++) {
        const float* rp = &s_in[(c*21 + gy*2 + kh)*72 + gx*8];
        float4 a0 = *(const float4*)(rp);
        float4 a1 = *(const float4*)(rp + 4);
        float4 a2 = *(const float4*)(rp + 8);
        float in13[13] = {a0.x,a0.y,a0.z,a0.w, a1.x,a1.y,a1.z,a1.w,
                          a2.x,a2.y,a2.z,a2.w, rp[12]};
        const float* wp = &s_w[((c*7 + kh)*7)*16 + og*4];
#pragma unroll
        for (int kw = 0; kw < 7; kw++) {
            float4 wv = *(const float4*)(wp + kw*16);
            u64 w01 = pack2(wv.x, wv.y);
            u64 w23 = pack2(wv.z, wv.w);
#pragma unroll
            for (int j = 0; j < 4; j++) {
                float v = in13[kw + 2*j];
                u64 vv = pack2(v, v);
                ffma2(acc2[0][j], w01, vv);
                ffma2(acc2[1][j], w23, vv);
            }
        }
    }

    // unpack to scalar accumulators
    float accf[4][4];
#pragma unroll
    for (int p = 0; p < 2; p++)
#pragma unroll
        for (int j = 0; j < 4; j++) {
            float2 f2 = unpack2(acc2[p][j]);
            accf[2*p][j]   = f2.x;
            accf[2*p+1][j] = f2.y;
        }

    // store
    const int oh  = blockIdx.y*8 + gy;
    const int ow0 = blockIdx.x*32 + gx*4;
#pragma unroll
    for (int o = 0; o < 4; o++) {
        int base = ((b*64 + oc0 + og*4 + o)*256 + oh)*256 + ow0;
        float4 st = make_float4(accf[o][0], accf[o][1], accf[o][2], accf[o][3]);
        *(float4*)&g_stem_out[base] = st;
    }

    // fused BN stats: per-thread sums over the 4 cols, reduce over block
    float red[8];
#pragma unroll
    for (int o = 0; o < 4; o++) {
        float s = 0.0f, q = 0.0f;
#pragma unroll
        for (int j = 0; j < 4; j++) {
            float v = accf[o][j];
            s += v; q = fmaf(v, v, q);
        }
        red[o] = s; red[4 + o] = q;
    }
#pragma unroll
    for (int off = 16; off; off >>= 1)
#pragma unroll
        for (int r = 0; r < 8; r++)
            red[r] += __shfl_down_sync(0xffffffffu, red[r], off);
    const int lane = tid & 31, wid = tid >> 5;
    if (lane == 0)
#pragma unroll
        for (int r = 0; r < 8; r++) s_red[wid][r] = red[r];
    __syncthreads();
    if (tid < 32) {
        int g2 = tid >> 3;          // oc group 0..3 (warps 2g2, 2g2+1)
        int r  = tid & 7;           // 0..3 sum, 4..7 sumsq
        float v = s_red[2*g2][r] + s_red[2*g2+1][r];
        int oc = oc0 + g2*4 + (r & 3);
        if (r < 4) atomicAdd(&g_psum[oc*16 + b], (double)v);
        else       atomicAdd(&g_psq [oc*16 + b], (double)v);
    }
}

__global__ void k_stem_prepare(const float* __restrict__ g,
                               const float* __restrict__ bb) {
    int c = threadIdx.x;
    double s = 0.0, q = 0.0;
    for (int b = 0; b < 16; b++) { s += g_psum[c*16 + b]; q += g_psq[c*16 + b]; }
    double N = 1048576.0;
    double mean = s / N;
    double var  = q / N - mean*mean;
    float sc = g[c] * rsqrtf((float)var + 1e-5f);
    g_sscale[c] = sc;
    g_sshift[c] = bb[c] - (float)mean * sc;
}

// ---------------- BN apply + relu + maxpool 3x3 s2 p1 -> f ---------------------
__global__ void k_stem_pool() {
    __shared__ float s[17*66];
    const int z = blockIdx.z;           // b*64 + c
    const float sc = g_sscale[z & 63], sh = g_sshift[z & 63];
    const float* p = g_stem_out + (size_t)z*65536;
    const int y0 = blockIdx.y*8, x0 = blockIdx.x*32;
    const int ihb = 2*y0 - 1, iwb = 2*x0 - 1;
    for (int i = threadIdx.x; i < 17*65; i += 256) {
        int r = i / 65, cc = i % 65;
        int ih = ihb + r, iw = iwb + cc;
        float v = 0.0f;
        if ((unsigned)ih < 256u && (unsigned)iw < 256u)
            v = fmaxf(fmaf(p[ih*256 + iw], sc, sh), 0.0f);
        s[r*66 + cc] = v;
    }
    __syncthreads();
    int tx = threadIdx.x & 31, ty = threadIdx.x >> 5;
    float m = 0.0f;
#pragma unroll
    for (int dr = 0; dr < 3; dr++)
#pragma unroll
        for (int dc = 0; dc < 3; dc++)
            m = fmaxf(m, s[(2*ty + dr)*66 + 2*tx + dc]);
    g_f[(size_t)z*16384 + (y0 + ty)*128 + x0 + tx] = m;
}

// ---------------- grid_sample (±5° rotation) -> xt1/xt2 ------------------------
__device__ __forceinline__ float gs_tap(const float* p, float yy, float xx) {
    bool v = (xx >= 0.0f) && (xx < 128.0f) && (yy >= 0.0f) && (yy < 128.0f);
    int xi = (int)fminf(fmaxf(xx, 0.0f), 127.0f);
    int yi = (int)fminf(fmaxf(yy, 0.0f), 127.0f);
    return v ? p[yi*128 + xi] : 0.0f;
}

__global__ void k_gridsample() {
    const int z = blockIdx.z;
    const int t = z >> 10;              // 0: theta1, 1: theta2
    const int bc = z & 1023;            // b*64 + c
    const int x = blockIdx.x*32 + (threadIdx.x & 31);
    const int y = blockIdx.y*8  + (threadIdx.x >> 5);
    const float C0 = 0.99619469809174553f;
    const float S5 = 0.08715574274765817f;
    float gx = (2*x + 1)*(1.0f/128.0f) - 1.0f;
    float gy = (2*y + 1)*(1.0f/128.0f) - 1.0f;
    float sg = t ? -S5 : S5;
    float gxp =  C0*gx + sg*gy;
    float gyp = -sg*gx + C0*gy;
    float ix = ((gxp + 1.0f)*128.0f - 1.0f)*0.5f;
    float iy = ((gyp + 1.0f)*128.0f - 1.0f)*0.5f;
    float x0f = floorf(ix), y0f = floorf(iy);
    float lx = ix - x0f, ly = iy - y0f;
    const float* p = g_f + (size_t)bc*16384;
    float r = gs_tap(p, y0f,        x0f)        * (1.0f - lx)*(1.0f - ly)
            + gs_tap(p, y0f + 1.0f, x0f)        * (1.0f - lx)*ly
            + gs_tap(p, y0f,        x0f + 1.0f) * lx*(1.0f - ly)
            + gs_tap(p, y0f + 1.0f, x0f + 1.0f) * lx*ly;
    g_xt[(size_t)t*16777216 + (size_t)bc*16384 + y*128 + x] = r;
}

// ---------------- roialign -> h (16, 704, 23, 23) ------------------------------
__global__ void k_roialign(const float* __restrict__ box) {
    int idx = blockIdx.x*256 + threadIdx.x;
    if (idx >= 64*529) return;
    const int c  = idx / 529;
    const int sp = idx % 529;
    const int ph = sp / 23, pw = sp % 23;
    const int combo = blockIdx.y, b = blockIdx.z;

    const float* src; int slot, choff;
    if (combo < 7) { src = g_f; slot = combo; choff = combo*64; }
    else {
        int k2 = combo - 7;
        src = g_xt + (size_t)(k2 >> 1)*16777216;
        slot = k2 & 1; choff = 448 + k2*64;
    }
    const float* bp = box + b*28 + slot*4;
    float x1 = bp[0]*0.25f, y1 = bp[1]*0.25f;
    float x2 = bp[2]*0.25f, y2 = bp[3]*0.25f;
    float bw = fmaxf(x2 - x1, 1.0f) / 23.0f;
    float bh = fmaxf(y2 - y1, 1.0f) / 23.0f;
    const float* p = src + (size_t)(b*64 + c)*16384;

    float acc = 0.0f;
#pragma unroll
    for (int oi = 0; oi < 2; oi++)
#pragma unroll
    for (int oj = 0; oj < 2; oj++) {
        float py = (float)ph + (oi*0.5f + 0.25f);
        float px = (float)pw + (oj*0.5f + 0.25f);
        float yv = y1 + py*bh;
        float xv = x1 + px*bw;
        bool empty = (yv < -1.0f) || (yv > 128.0f) || (xv < -1.0f) || (xv > 128.0f);
        float yc = fminf(fmaxf(yv, 0.0f), 127.0f);
        float xc = fminf(fmaxf(xv, 0.0f), 127.0f);
        float y0f = floorf(yc), x0f = floorf(xc);
        int yi = (int)y0f, xi = (int)x0f;
        int yi1 = min(yi + 1, 127), xi1 = min(xi + 1, 127);
        float ly = yc - y0f, lx = xc - x0f;
        float hy = 1.0f - ly, hx = 1.0f - lx;
        float v = p[yi*128  + xi ] * hy*hx + p[yi*128  + xi1] * hy*lx
                + p[yi1*128 + xi ] * ly*hx + p[yi1*128 + xi1] * ly*lx;
        acc += empty ? 0.0f : v;
    }
    g_h[((size_t)(b*704 + choff + c))*529 + sp] = acc * 0.25f;
}

// ---------------- conv1: 3x3 p0, 704->64, 23x23 -> 21x21 -----------------------
// grid (2 cin-splits, 8 oc-groups, 16 b); block 448 thr (441 active spatial)
// FFMA2 over oc-pairs (weight float4 loads give adjacent register pairs free)
__global__ __launch_bounds__(448) void k_conv1(const float* __restrict__ w) {
    __shared__ float s_in[4416];   // [8][23][24]
    __shared__ float s_w[576];     // [(c8*9+kh*3+kw)][8 oc]
    const int tid = threadIdx.x;
    const int split = blockIdx.x, ocg = blockIdx.y, b = blockIdx.z;
    const int oc0 = ocg*8;
    const int y = tid / 21, x = tid % 21;
    const bool act = tid < 441;
    u64 acc2[4];
#pragma unroll
    for (int o = 0; o < 4; o++) acc2[o] = 0ull;

    for (int cc = split*352; cc < split*352 + 352; cc += 8) {
        __syncthreads();
        for (int i = tid; i < 8*529; i += 448) {
            int c8 = i / 529, r = i % 529;
            s_in[(c8*23 + r/23)*24 + r%23] = g_h[((size_t)(b*704 + cc + c8))*529 + r];
        }
        for (int i = tid; i < 576; i += 448) {
            int oc = i & 7, r = i >> 3;
            s_w[i] = w[(oc0 + oc)*6336 + (cc + r/9)*9 + r%9];
        }
        __syncthreads();
        if (act) {
#pragma unroll
            for (int c8 = 0; c8 < 8; c8++) {
#pragma unroll
                for (int kh = 0; kh < 3; kh++) {
                    const float* rp = &s_in[(c8*23 + y + kh)*24 + x];
                    float v0 = rp[0], v1 = rp[1], v2 = rp[2];
                    const float* wp = &s_w[(c8*9 + kh*3)*8];
#pragma unroll
                    for (int kw = 0; kw < 3; kw++) {
                        float v = (kw == 0) ? v0 : (kw == 1) ? v1 : v2;
                        u64 vv = pack2(v, v);
                        float4 wa = *(const float4*)(wp + kw*8);
                        float4 wb = *(const float4*)(wp + kw*8 + 4);
                        u64 w0 = pack2(wa.x, wa.y);
                        u64 w1 = pack2(wa.z, wa.w);
                        u64 w2 = pack2(wb.x, wb.y);
                        u64 w3 = pack2(wb.z, wb.w);
                        ffma2(acc2[0], w0, vv);
                        ffma2(acc2[1], w1, vv);
                        ffma2(acc2[2], w2, vv);
                        ffma2(acc2[3], w3, vv);
                    }
                }
            }
        }
    }
    if (act) {
#pragma unroll
        for (int o = 0; o < 4; o++) {
            float2 f2 = unpack2(acc2[o]);
            atomicAdd(&g_c1[((size_t)(b*64 + oc0 + 2*o    ))*441 + tid], f2.x);
            atomicAdd(&g_c1[((size_t)(b*64 + oc0 + 2*o + 1))*441 + tid], f2.y);
        }
    }
}

// ---------------- bn1 stats (conv1_b cancels inside BN; skipped) ---------------
__global__ void k_bn1stats(const float* __restrict__ g, const float* __restrict__ bb) {
    const int c = blockIdx.x;
    float s = 0.0f, q = 0.0f;
    for (int i = threadIdx.x; i < 7056; i += 256) {
        int b = i / 441, sp = i % 441;
        float v = g_c1[((size_t)(b*64 + c))*441 + sp];
        s += v; q += v*v;
    }
#pragma unroll
    for (int off = 16; off; off >>= 1) {
        s += __shfl_down_sync(0xffffffffu, s, off);
        q += __shfl_down_sync(0xffffffffu, q, off);
    }
    __shared__ float w1[8], w2[8];
    int lane = threadIdx.x & 31, wid = threadIdx.x >> 5;
    if (lane == 0) { w1[wid] = s; w2[wid] = q; }
    __syncthreads();
    if (threadIdx.x == 0) {
        float ts = 0.0f, tq = 0.0f;
        for (int i = 0; i < 8; i++) { ts += w1[i]; tq += w2[i]; }
        float mean = ts / 7056.0f;
        float var  = tq / 7056.0f - mean*mean;
        float sc = g[c] * rsqrtf(var + 1e-5f);
        g_b1scale[c] = sc;
        g_b1shift[c] = bb[c] - mean*sc;
    }
}

// ---------------- bn1 apply + relu + maxpool 2x2 s2 ----------------------------
__global__ void k_pool2() {
    int idx = blockIdx.x*256 + threadIdx.x;
    if (idx >= BATCH*64*100) return;
    int b = idx / 6400, r = idx % 6400;
    int c = r / 100, sxy = r % 100;
    int y = sxy / 10, x = sxy % 10;
    float sc = g_b1scale[c], sh = g_b1shift[c];
    const float* p = g_c1 + (size_t)(b*64 + c)*441;
    float m = -1e30f;
#pragma unroll
    for (int dr = 0; dr < 2; dr++)
#pragma unroll
        for (int dc = 0; dc < 2; dc++) {
            float v = fmaxf(fmaf(p[(2*y + dr)*21 + 2*x + dc], sc, sh), 0.0f);
            m = fmaxf(m, v);
        }
    g_p1[idx] = m;
}

// ---------------- conv2: 3x3 p0, 64->32, 10x10 -> 8x8, +bias, relu ------------
__global__ void k_conv2(const float* __restrict__ w, const float* __restrict__ bias) {
    __shared__ float s_in[3200];   // [32][10][10]
    __shared__ float s_w[2304];    // [(c*9+t)][8 oc]
    const int tid = threadIdx.x;
    const int ocg = blockIdx.x, b = blockIdx.y;
    const int oc0 = ocg*8;
    const int s = tid & 63, og = tid >> 6;
    const int y = s >> 3, x = s & 7;
    float acc[2] = {0.0f, 0.0f};

    for (int cc = 0; cc < 64; cc += 32) {
        __syncthreads();
        for (int i = tid; i < 3200; i += 256)
            s_in[i] = g_p1[((size_t)(b*64 + cc))*100 + i];
        for (int i = tid; i < 2304; i += 256) {
            int oc = i & 7, r = i >> 3;
            s_w[i] = w[(oc0 + oc)*576 + (cc + r/9)*9 + r%9];
        }
        __syncthreads();
#pragma unroll 4
        for (int c = 0; c < 32; c++) {
#pragma unroll
            for (int kh = 0; kh < 3; kh++) {
                const float* rp = &s_in[(c*10 + y + kh)*10 + x];
                float v0 = rp[0], v1 = rp[1], v2 = rp[2];
                const float* wp = &s_w[(c*9 + kh*3)*8 + og*2];
                acc[0] = fmaf(wp[0],  v0, acc[0]); acc[1] = fmaf(wp[1],  v0, acc[1]);
                acc[0] = fmaf(wp[8],  v1, acc[0]); acc[1] = fmaf(wp[9],  v1, acc[1]);
                acc[0] = fmaf(wp[16], v2, acc[0]); acc[1] = fmaf(wp[17], v2, acc[1]);
            }
        }
    }
#pragma unroll
    for (int o = 0; o < 2; o++) {
        int oc = oc0 + og*2 + o;
        g_fcin[b*2048 + oc*64 + s] = fmaxf(acc[o] + bias[oc], 0.0f);
    }
}

// ---------------- fc1: (16,2048) x (128,2048)^T + b, relu ----------------------
__global__ void k_fc1(const float* __restrict__ w, const float* __restrict__ bias) {
    const int j = blockIdx.x;
    float acc[16];
#pragma unroll
    for (int b = 0; b < 16; b++) acc[b] = 0.0f;
    for (int k = threadIdx.x; k < 2048; k += 256) {
        float wv = w[j*2048 + k];
#pragma unroll
        for (int b = 0; b < 16; b++)
            acc[b] = fmaf(wv, g_fcin[b*2048 + k], acc[b]);
    }
#pragma unroll
    for (int off = 16; off; off >>= 1)
#pragma unroll
        for (int b = 0; b < 16; b++)
            acc[b] += __shfl_down_sync(0xffffffffu, acc[b], off);
    __shared__ float red[8][16];
    int lane = threadIdx.x & 31, wid = threadIdx.x >> 5;
    if (lane == 0)
#pragma unroll
        for (int b = 0; b < 16; b++) red[wid][b] = acc[b];
    __syncthreads();
    if (threadIdx.x < 16) {
        float sv = 0.0f;
        for (int wdx = 0; wdx < 8; wdx++) sv += red[wdx][threadIdx.x];
        g_fc1v[threadIdx.x*128 + j] = fmaxf(sv + bias[j], 0.0f);
    }
}

// ---------------- head + tanh --------------------------------------------------
__global__ void k_head(const float* __restrict__ w, const float* __restrict__ bias,
                       float* __restrict__ out) {
    int t = threadIdx.x;          // 192 threads
    int b = t / 12, j = t % 12;
    float s = bias[j];
    for (int k = 0; k < 128; k++)
        s = fmaf(g_fc1v[b*128 + k], w[j*128 + k], s);
    out[t] = tanhf(s);
}

// ---------------- launch -------------------------------------------------------
extern "C" void kernel_launch(void* const* d_in, const int* in_sizes, int n_in,
                              void* d_out, int out_size) {
    const float* x       = (const float*)d_in[0];
    const float* box     = (const float*)d_in[1];
    const float* stem_w  = (const float*)d_in[2];
    const float* stem_g  = (const float*)d_in[3];
    const float* stem_b  = (const float*)d_in[4];
    const float* conv1_w = (const float*)d_in[5];
    /* conv1_b (d_in[6]) cancels exactly inside batchnorm — unused */
    const float* bn1_g   = (const float*)d_in[7];
    const float* bn1_b   = (const float*)d_in[8];
    const float* conv2_w = (const float*)d_in[9];
    const float* conv2_b = (const float*)d_in[10];
    const float* fc1_w   = (const float*)d_in[11];
    const float* fc1_b   = (const float*)d_in[12];
    const float* head_w  = (const float*)d_in[13];
    const float* head_b  = (const float*)d_in[14];
    float* out = (float*)d_out;

    k_zero<<<512, 256>>>();
    k_stem_conv<<<dim3(8, 32, 64), 256>>>(x, stem_w);
    k_stem_prepare<<<1, 64>>>(stem_g, stem_b);
    k_stem_pool<<<dim3(4, 16, 1024), 256>>>();
    k_gridsample<<<dim3(4, 16, 2048), 256>>>();
    k_roialign<<<dim3(133, 11, 16), 256>>>(box);
    k_conv1<<<dim3(2, 8, 16), 448>>>(conv1_w);
    k_bn1stats<<<64, 256>>>(bn1_g, bn1_b);
    k_pool2<<<400, 256>>>();
    k_conv2<<<dim3(4, 16), 256>>>(conv2_w, conv2_b);
    k_fc1<<<128, 256>>>(fc1_w, fc1_b);
    k_head<<<1, 192>>>(head_w, head_b, out);
}

// round 11
// speedup vs baseline: 1.1719x; 1.1666x over previous
#include <cuda_runtime.h>
#include <math.h>

// ---------------- scratch (device globals; no allocations allowed) -------------
#define BATCH 16
__device__ float  g_stem_out[BATCH*64*256*256];   // conv-stem output (NCHW)
__device__ float  g_f[BATCH*64*128*128];          // f after BN+relu+maxpool
__device__ float  g_h[BATCH*704*529];             // concat roialign features
__device__ float  g_c1[BATCH*64*441];             // conv1 output (21x21)
__device__ float  g_p1[BATCH*64*100];             // after bn1+relu+pool (10x10)
__device__ float  g_fcin[BATCH*2048];             // conv2+relu, flattened
__device__ float  g_fc1v[BATCH*128];              // fc1+relu
__device__ double g_psum[64*16];                  // per (c,b) partial BN sums
__device__ double g_psq [64*16];
__device__ float  g_sscale[64], g_sshift[64];
__device__ float  g_b1scale[64], g_b1shift[64];

// ---------------- packed f32x2 helpers -----------------------------------------
typedef unsigned long long u64;
__device__ __forceinline__ u64 pack2(float lo, float hi) {
    u64 r; asm("mov.b64 %0,{%1,%2};" : "=l"(r) : "f"(lo), "f"(hi)); return r;
}
__device__ __forceinline__ void ffma2(u64& d, u64 a, u64 b) {
    asm("fma.rn.f32x2 %0,%1,%2,%0;" : "+l"(d) : "l"(a), "l"(b));
}
__device__ __forceinline__ float2 unpack2(u64 v) {
    float2 r; asm("mov.b64 {%0,%1},%2;" : "=f"(r.x), "=f"(r.y) : "l"(v)); return r;
}

// ---------------- zero accumulators (needed every graph replay) ----------------
__global__ void k_zero() {
    int idx = blockIdx.x * 256 + threadIdx.x;
    if (idx < 1024) { g_psum[idx] = 0.0; g_psq[idx] = 0.0; }
    for (int i = idx; i < BATCH*64*441; i += gridDim.x * 256) g_c1[i] = 0.0f;
}

// ---------------- stem conv: 7x7 s2 p3, NHWC in -> NCHW out --------------------
__global__ __launch_bounds__(256) void k_stem_conv(const float* __restrict__ x,
                                                   const float* __restrict__ w) {
    __shared__ float s_in[3*21*72];   // [c][21][72], 69 cols used
    __shared__ float s_w[2352];       // [(c*7+kh)*7+kw][16 oc]
    __shared__ float s_red[8][8];     // per-warp stats partials
    const int tid = threadIdx.x;
    const int b   = blockIdx.z >> 2;
    const int oc0 = (blockIdx.z & 3) * 16;
    const int base_ih = blockIdx.y * 16 - 3;
    const int base_iw = blockIdx.x * 64 - 3;

    for (int i = tid; i < 3*21*69; i += 256) {
        int c = i % 3, t = i / 3, ww = t % 69, hh = t / 69;
        int ih = base_ih + hh, iw = base_iw + ww;
        float v = 0.0f;
        if ((unsigned)ih < 512u && (unsigned)iw < 512u)
            v = x[((b*512 + ih)*512 + iw)*3 + c];
        s_in[(c*21 + hh)*72 + ww] = v;
    }
    for (int i = tid; i < 2352; i += 256) {
        int oc = i & 15, r = i >> 4;
        s_w[i] = w[(oc0 + oc)*147 + r];
    }
    __syncthreads();

    const int gx = tid & 7, gy = (tid >> 3) & 7, og = tid >> 6;
    u64 acc2[2][4];
#pragma unroll
    for (int p = 0; p < 2; p++)
#pragma unroll
        for (int j = 0; j < 4; j++) acc2[p][j] = 0ull;

#pragma unroll
    for (int c = 0; c < 3; c++)
#pragma unroll
    for (int kh = 0; kh < 7; kh++) {
        const float* rp = &s_in[(c*21 + gy*2 + kh)*72 + gx*8];
        float4 a0 = *(const float4*)(rp);
        float4 a1 = *(const float4*)(rp + 4);
        float4 a2 = *(const float4*)(rp + 8);
        float in13[13] = {a0.x,a0.y,a0.z,a0.w, a1.x,a1.y,a1.z,a1.w,
                          a2.x,a2.y,a2.z,a2.w, rp[12]};
        const float* wp = &s_w[((c*7 + kh)*7)*16 + og*4];
#pragma unroll
        for (int kw = 0; kw < 7; kw++) {
            float4 wv = *(const float4*)(wp + kw*16);
            u64 w01 = pack2(wv.x, wv.y);
            u64 w23 = pack2(wv.z, wv.w);
#pragma unroll
            for (int j = 0; j < 4; j++) {
                float v = in13[kw + 2*j];
                u64 vv = pack2(v, v);
                ffma2(acc2[0][j], w01, vv);
                ffma2(acc2[1][j], w23, vv);
            }
        }
    }

    float accf[4][4];
#pragma unroll
    for (int p = 0; p < 2; p++)
#pragma unroll
        for (int j = 0; j < 4; j++) {
            float2 f2 = unpack2(acc2[p][j]);
            accf[2*p][j]   = f2.x;
            accf[2*p+1][j] = f2.y;
        }

    const int oh  = blockIdx.y*8 + gy;
    const int ow0 = blockIdx.x*32 + gx*4;
#pragma unroll
    for (int o = 0; o < 4; o++) {
        int base = ((b*64 + oc0 + og*4 + o)*256 + oh)*256 + ow0;
        float4 st = make_float4(accf[o][0], accf[o][1], accf[o][2], accf[o][3]);
        *(float4*)&g_stem_out[base] = st;
    }

    // fused BN stats
    float red[8];
#pragma unroll
    for (int o = 0; o < 4; o++) {
        float s = 0.0f, q = 0.0f;
#pragma unroll
        for (int j = 0; j < 4; j++) {
            float v = accf[o][j];
            s += v; q = fmaf(v, v, q);
        }
        red[o] = s; red[4 + o] = q;
    }
#pragma unroll
    for (int off = 16; off; off >>= 1)
#pragma unroll
        for (int r = 0; r < 8; r++)
            red[r] += __shfl_down_sync(0xffffffffu, red[r], off);
    const int lane = tid & 31, wid = tid >> 5;
    if (lane == 0)
#pragma unroll
        for (int r = 0; r < 8; r++) s_red[wid][r] = red[r];
    __syncthreads();
    if (tid < 32) {
        int g2 = tid >> 3;
        int r  = tid & 7;
        float v = s_red[2*g2][r] + s_red[2*g2+1][r];
        int oc = oc0 + g2*4 + (r & 3);
        if (r < 4) atomicAdd(&g_psum[oc*16 + b], (double)v);
        else       atomicAdd(&g_psq [oc*16 + b], (double)v);
    }
}

__global__ void k_stem_prepare(const float* __restrict__ g,
                               const float* __restrict__ bb) {
    int c = threadIdx.x;
    double s = 0.0, q = 0.0;
    for (int b = 0; b < 16; b++) { s += g_psum[c*16 + b]; q += g_psq[c*16 + b]; }
    double N = 1048576.0;
    double mean = s / N;
    double var  = q / N - mean*mean;
    float sc = g[c] * rsqrtf((float)var + 1e-5f);
    g_sscale[c] = sc;
    g_sshift[c] = bb[c] - (float)mean * sc;
}

// ---------------- BN apply + relu + maxpool 3x3 s2 p1 -> f ---------------------
// one thread per pooled output; 9 predicated gathers; pure shift/mask indexing.
__global__ __launch_bounds__(256) void k_stem_pool() {
    const int idx = blockIdx.x*256 + threadIdx.x;   // 16 * 64 * 128 * 128
    const int px = idx & 127;
    const int py = (idx >> 7) & 127;
    const int z  = idx >> 14;                       // b*64 + c
    const float sc = g_sscale[z & 63], sh = g_sshift[z & 63];
    const float* p = g_stem_out + (size_t)z*65536;
    const int iy0 = 2*py - 1, ix0 = 2*px - 1;
    float m = 0.0f;   // post-relu values are >= 0, so 0 is a safe identity
#pragma unroll
    for (int dr = 0; dr < 3; dr++) {
        int iy = iy0 + dr;
        if (iy < 0) continue;            // iy <= 255 always
        const float* row = p + iy*256;
#pragma unroll
        for (int dc = 0; dc < 3; dc++) {
            int ix = ix0 + dc;
            if (ix < 0) continue;        // ix <= 255 always
            float v = fmaf(row[ix], sc, sh);
            m = fmaxf(m, v);
        }
    }
    g_f[idx] = fmaxf(m, 0.0f);
}

// ---------------- on-the-fly grid_sample (±5° rotation) ------------------------
__device__ __forceinline__ float gs_tap(const float* p, float yy, float xx) {
    bool v = (xx >= 0.0f) && (xx < 128.0f) && (yy >= 0.0f) && (yy < 128.0f);
    int xi = (int)fminf(fmaxf(xx, 0.0f), 127.0f);
    int yi = (int)fminf(fmaxf(yy, 0.0f), 127.0f);
    return v ? p[yi*128 + xi] : 0.0f;
}

// value the old k_gridsample would have written at integer pixel (yy, xx)
__device__ __forceinline__ float gs_eval(const float* __restrict__ p, int t,
                                         int yy, int xx) {
    const float C0 = 0.99619469809174553f;
    const float S5 = 0.08715574274765817f;
    float gx = (2*xx + 1)*(1.0f/128.0f) - 1.0f;
    float gy = (2*yy + 1)*(1.0f/128.0f) - 1.0f;
    float sg = t ? -S5 : S5;
    float gxp =  C0*gx + sg*gy;
    float gyp = -sg*gx + C0*gy;
    float ix = ((gxp + 1.0f)*128.0f - 1.0f)*0.5f;
    float iy = ((gyp + 1.0f)*128.0f - 1.0f)*0.5f;
    float x0f = floorf(ix), y0f = floorf(iy);
    float lx = ix - x0f, ly = iy - y0f;
    return gs_tap(p, y0f,        x0f)        * (1.0f - lx)*(1.0f - ly)
         + gs_tap(p, y0f + 1.0f, x0f)        * (1.0f - lx)*ly
         + gs_tap(p, y0f,        x0f + 1.0f) * lx*(1.0f - ly)
         + gs_tap(p, y0f + 1.0f, x0f + 1.0f) * lx*ly;
}

// ---------------- roialign -> h (16, 704, 23, 23) ------------------------------
// combos 0..6: sample f directly; combos 7..10: sample rotated feature computed
// on the fly (bit-identical to the old precomputed g_xt path).
__global__ void k_roialign(const float* __restrict__ box) {
    int idx = blockIdx.x*256 + threadIdx.x;
    if (idx >= 64*529) return;
    const int c  = idx / 529;
    const int sp = idx % 529;
    const int ph = sp / 23, pw = sp % 23;
    const int combo = blockIdx.y, b = blockIdx.z;

    const bool direct = (combo < 7);
    int slot, choff, t = 0;
    if (direct) { slot = combo; choff = combo*64; }
    else {
        int k2 = combo - 7;
        t = k2 >> 1;
        slot = k2 & 1; choff = 448 + k2*64;
    }
    const float* bp = box + b*28 + slot*4;
    float x1 = bp[0]*0.25f, y1 = bp[1]*0.25f;
    float x2 = bp[2]*0.25f, y2 = bp[3]*0.25f;
    float bw = fmaxf(x2 - x1, 1.0f) / 23.0f;
    float bh = fmaxf(y2 - y1, 1.0f) / 23.0f;
    const float* p = g_f + (size_t)(b*64 + c)*16384;

    float acc = 0.0f;
#pragma unroll
    for (int oi = 0; oi < 2; oi++)
#pragma unroll
    for (int oj = 0; oj < 2; oj++) {
        float py = (float)ph + (oi*0.5f + 0.25f);
        float px = (float)pw + (oj*0.5f + 0.25f);
        float yv = y1 + py*bh;
        float xv = x1 + px*bw;
        bool empty = (yv < -1.0f) || (yv > 128.0f) || (xv < -1.0f) || (xv > 128.0f);
        float yc = fminf(fmaxf(yv, 0.0f), 127.0f);
        float xc = fminf(fmaxf(xv, 0.0f), 127.0f);
        float y0f = floorf(yc), x0f = floorf(xc);
        int yi = (int)y0f, xi = (int)x0f;
        int yi1 = min(yi + 1, 127), xi1 = min(xi + 1, 127);
        float ly = yc - y0f, lx = xc - x0f;
        float hy = 1.0f - ly, hx = 1.0f - lx;
        float v;
        if (direct) {
            v = p[yi*128  + xi ] * hy*hx + p[yi*128  + xi1] * hy*lx
              + p[yi1*128 + xi ] * ly*hx + p[yi1*128 + xi1] * ly*lx;
        } else {
            v = gs_eval(p, t, yi,  xi ) * hy*hx + gs_eval(p, t, yi,  xi1) * hy*lx
              + gs_eval(p, t, yi1, xi ) * ly*hx + gs_eval(p, t, yi1, xi1) * ly*lx;
        }
        acc += empty ? 0.0f : v;
    }
    g_h[((size_t)(b*704 + choff + c))*529 + sp] = acc * 0.25f;
}

// ---------------- conv1: 3x3 p0, 704->64, 23x23 -> 21x21 -----------------------
__global__ __launch_bounds__(448) void k_conv1(const float* __restrict__ w) {
    __shared__ float s_in[4416];   // [8][23][24]
    __shared__ float s_w[576];     // [(c8*9+kh*3+kw)][8 oc]
    const int tid = threadIdx.x;
    const int split = blockIdx.x, ocg = blockIdx.y, b = blockIdx.z;
    const int oc0 = ocg*8;
    const int y = tid / 21, x = tid % 21;
    const bool act = tid < 441;
    u64 acc2[4];
#pragma unroll
    for (int o = 0; o < 4; o++) acc2[o] = 0ull;

    for (int cc = split*352; cc < split*352 + 352; cc += 8) {
        __syncthreads();
        for (int i = tid; i < 8*529; i += 448) {
            int c8 = i / 529, r = i % 529;
            s_in[(c8*23 + r/23)*24 + r%23] = g_h[((size_t)(b*704 + cc + c8))*529 + r];
        }
        for (int i = tid; i < 576; i += 448) {
            int oc = i & 7, r = i >> 3;
            s_w[i] = w[(oc0 + oc)*6336 + (cc + r/9)*9 + r%9];
        }
        __syncthreads();
        if (act) {
#pragma unroll
            for (int c8 = 0; c8 < 8; c8++) {
#pragma unroll
                for (int kh = 0; kh < 3; kh++) {
                    const float* rp = &s_in[(c8*23 + y + kh)*24 + x];
                    float v0 = rp[0], v1 = rp[1], v2 = rp[2];
                    const float* wp = &s_w[(c8*9 + kh*3)*8];
#pragma unroll
                    for (int kw = 0; kw < 3; kw++) {
                        float v = (kw == 0) ? v0 : (kw == 1) ? v1 : v2;
                        u64 vv = pack2(v, v);
                        float4 wa = *(const float4*)(wp + kw*8);
                        float4 wb = *(const float4*)(wp + kw*8 + 4);
                        u64 w0 = pack2(wa.x, wa.y);
                        u64 w1 = pack2(wa.z, wa.w);
                        u64 w2 = pack2(wb.x, wb.y);
                        u64 w3 = pack2(wb.z, wb.w);
                        ffma2(acc2[0], w0, vv);
                        ffma2(acc2[1], w1, vv);
                        ffma2(acc2[2], w2, vv);
                        ffma2(acc2[3], w3, vv);
                    }
                }
            }
        }
    }
    if (act) {
#pragma unroll
        for (int o = 0; o < 4; o++) {
            float2 f2 = unpack2(acc2[o]);
            atomicAdd(&g_c1[((size_t)(b*64 + oc0 + 2*o    ))*441 + tid], f2.x);
            atomicAdd(&g_c1[((size_t)(b*64 + oc0 + 2*o + 1))*441 + tid], f2.y);
        }
    }
}

// ---------------- bn1 stats --------------------------------------------------
__global__ void k_bn1stats(const float* __restrict__ g, const float* __restrict__ bb) {
    const int c = blockIdx.x;
    float s = 0.0f, q = 0.0f;
    for (int i = threadIdx.x; i < 7056; i += 256) {
        int b = i / 441, sp = i % 441;
        float v = g_c1[((size_t)(b*64 + c))*441 + sp];
        s += v; q += v*v;
    }
#pragma unroll
    for (int off = 16; off; off >>= 1) {
        s += __shfl_down_sync(0xffffffffu, s, off);
        q += __shfl_down_sync(0xffffffffu, q, off);
    }
    __shared__ float w1[8], w2[8];
    int lane = threadIdx.x & 31, wid = threadIdx.x >> 5;
    if (lane == 0) { w1[wid] = s; w2[wid] = q; }
    __syncthreads();
    if (threadIdx.x == 0) {
        float ts = 0.0f, tq = 0.0f;
        for (int i = 0; i < 8; i++) { ts += w1[i]; tq += w2[i]; }
        float mean = ts / 7056.0f;
        float var  = tq / 7056.0f - mean*mean;
        float sc = g[c] * rsqrtf(var + 1e-5f);
        g_b1scale[c] = sc;
        g_b1shift[c] = bb[c] - mean*sc;
    }
}

// ---------------- bn1 apply + relu + maxpool 2x2 s2 ----------------------------
__global__ void k_pool2() {
    int idx = blockIdx.x*256 + threadIdx.x;
    if (idx >= BATCH*64*100) return;
    int b = idx / 6400, r = idx % 6400;
    int c = r / 100, sxy = r % 100;
    int y = sxy / 10, x = sxy % 10;
    float sc = g_b1scale[c], sh = g_b1shift[c];
    const float* p = g_c1 + (size_t)(b*64 + c)*441;
    float m = -1e30f;
#pragma unroll
    for (int dr = 0; dr < 2; dr++)
#pragma unroll
        for (int dc = 0; dc < 2; dc++) {
            float v = fmaxf(fmaf(p[(2*y + dr)*21 + 2*x + dc], sc, sh), 0.0f);
            m = fmaxf(m, v);
        }
    g_p1[idx] = m;
}

// ---------------- conv2: 3x3 p0, 64->32, 10x10 -> 8x8, +bias, relu ------------
__global__ void k_conv2(const float* __restrict__ w, const float* __restrict__ bias) {
    __shared__ float s_in[3200];   // [32][10][10]
    __shared__ float s_w[2304];    // [(c*9+t)][8 oc]
    const int tid = threadIdx.x;
    const int ocg = blockIdx.x, b = blockIdx.y;
    const int oc0 = ocg*8;
    const int s = tid & 63, og = tid >> 6;
    const int y = s >> 3, x = s & 7;
    float acc[2] = {0.0f, 0.0f};

    for (int cc = 0; cc < 64; cc += 32) {
        __syncthreads();
        for (int i = tid; i < 3200; i += 256)
            s_in[i] = g_p1[((size_t)(b*64 + cc))*100 + i];
        for (int i = tid; i < 2304; i += 256) {
            int oc = i & 7, r = i >> 3;
            s_w[i] = w[(oc0 + oc)*576 + (cc + r/9)*9 + r%9];
        }
        __syncthreads();
#pragma unroll 4
        for (int c = 0; c < 32; c++) {
#pragma unroll
            for (int kh = 0; kh < 3; kh++) {
                const float* rp = &s_in[(c*10 + y + kh)*10 + x];
                float v0 = rp[0], v1 = rp[1], v2 = rp[2];
                const float* wp = &s_w[(c*9 + kh*3)*8 + og*2];
                acc[0] = fmaf(wp[0],  v0, acc[0]); acc[1] = fmaf(wp[1],  v0, acc[1]);
                acc[0] = fmaf(wp[8],  v1, acc[0]); acc[1] = fmaf(wp[9],  v1, acc[1]);
                acc[0] = fmaf(wp[16], v2, acc[0]); acc[1] = fmaf(wp[17], v2, acc[1]);
            }
        }
    }
#pragma unroll
    for (int o = 0; o < 2; o++) {
        int oc = oc0 + og*2 + o;
        g_fcin[b*2048 + oc*64 + s] = fmaxf(acc[o] + bias[oc], 0.0f);
    }
}

// ---------------- fc1: (16,2048) x (128,2048)^T + b, relu ----------------------
__global__ void k_fc1(const float* __restrict__ w, const float* __restrict__ bias) {
    const int j = blockIdx.x;
    float acc[16];
#pragma unroll
    for (int b = 0; b < 16; b++) acc[b] = 0.0f;
    for (int k = threadIdx.x; k < 2048; k += 256) {
        float wv = w[j*2048 + k];
#pragma unroll
        for (int b = 0; b < 16; b++)
            acc[b] = fmaf(wv, g_fcin[b*2048 + k], acc[b]);
    }
#pragma unroll
    for (int off = 16; off; off >>= 1)
#pragma unroll
        for (int b = 0; b < 16; b++)
            acc[b] += __shfl_down_sync(0xffffffffu, acc[b], off);
    __shared__ float red[8][16];
    int lane = threadIdx.x & 31, wid = threadIdx.x >> 5;
    if (lane == 0)
#pragma unroll
        for (int b = 0; b < 16; b++) red[wid][b] = acc[b];
    __syncthreads();
    if (threadIdx.x < 16) {
        float sv = 0.0f;
        for (int wdx = 0; wdx < 8; wdx++) sv += red[wdx][threadIdx.x];
        g_fc1v[threadIdx.x*128 + j] = fmaxf(sv + bias[j], 0.0f);
    }
}

// ---------------- head + tanh --------------------------------------------------
__global__ void k_head(const float* __restrict__ w, const float* __restrict__ bias,
                       float* __restrict__ out) {
    int t = threadIdx.x;          // 192 threads
    int b = t / 12, j = t % 12;
    float s = bias[j];
    for (int k = 0; k < 128; k++)
        s = fmaf(g_fc1v[b*128 + k], w[j*128 + k], s);
    out[t] = tanhf(s);
}

// ---------------- launch -------------------------------------------------------
extern "C" void kernel_launch(void* const* d_in, const int* in_sizes, int n_in,
                              void* d_out, int out_size) {
    const float* x       = (const float*)d_in[0];
    const float* box     = (const float*)d_in[1];
    const float* stem_w  = (const float*)d_in[2];
    const float* stem_g  = (const float*)d_in[3];
    const float* stem_b  = (const float*)d_in[4];
    const float* conv1_w = (const float*)d_in[5];
    /* conv1_b (d_in[6]) cancels exactly inside batchnorm — unused */
    const float* bn1_g   = (const float*)d_in[7];
    const float* bn1_b   = (const float*)d_in[8];
    const float* conv2_w = (const float*)d_in[9];
    const float* conv2_b = (const float*)d_in[10];
    const float* fc1_w   = (const float*)d_in[11];
    const float* fc1_b   = (const float*)d_in[12];
    const float* head_w  = (const float*)d_in[13];
    const float* head_b  = (const float*)d_in[14];
    float* out = (float*)d_out;

    k_zero<<<512, 256>>>();
    k_stem_conv<<<dim3(8, 32, 64), 256>>>(x, stem_w);
    k_stem_prepare<<<1, 64>>>(stem_g, stem_b);
    k_stem_pool<<<65536, 256>>>();
    k_roialign<<<dim3(133, 11, 16), 256>>>(box);
    k_conv1<<<dim3(2, 8, 16), 448>>>(conv1_w);
    k_bn1stats<<<64, 256>>>(bn1_g, bn1_b);
    k_pool2<<<400, 256>>>();
    k_conv2<<<dim3(4, 16), 256>>>(conv2_w, conv2_b);
    k_fc1<<<128, 256>>>(fc1_w, fc1_b);
    k_head<<<1, 192>>>(head_w, head_b, out);
}

// round 12
// speedup vs baseline: 1.2017x; 1.0254x over previous
#include <cuda_runtime.h>
#include <math.h>

// ---------------- scratch (device globals; no allocations allowed) -------------
#define BATCH 16
__device__ float  g_stem_out[BATCH*64*256*256];   // conv-stem output (NCHW)
__device__ float  g_f[BATCH*64*128*128];          // f after BN+relu+maxpool
__device__ float  g_h[BATCH*704*529];             // concat roialign features
__device__ float  g_c1[BATCH*64*441];             // conv1 output (21x21)
__device__ float  g_p1[BATCH*64*100];             // after bn1+relu+pool (10x10)
__device__ float  g_fcin[BATCH*2048];             // conv2+relu, flattened
__device__ float  g_fc1v[BATCH*128];              // fc1+relu
__device__ double g_psum[64*16];                  // per (c,b) partial BN sums
__device__ double g_psq [64*16];
__device__ float  g_sscale[64], g_sshift[64];
__device__ float  g_b1scale[64], g_b1shift[64];

// ---------------- packed f32x2 helpers -----------------------------------------
typedef unsigned long long u64;
__device__ __forceinline__ u64 pack2(float lo, float hi) {
    u64 r; asm("mov.b64 %0,{%1,%2};" : "=l"(r) : "f"(lo), "f"(hi)); return r;
}
__device__ __forceinline__ void ffma2(u64& d, u64 a, u64 b) {
    asm("fma.rn.f32x2 %0,%1,%2,%0;" : "+l"(d) : "l"(a), "l"(b));
}
__device__ __forceinline__ float2 unpack2(u64 v) {
    float2 r; asm("mov.b64 {%0,%1},%2;" : "=f"(r.x), "=f"(r.y) : "l"(v)); return r;
}

// ---------------- zero accumulators (needed every graph replay) ----------------
__global__ void k_zero() {
    int idx = blockIdx.x * 256 + threadIdx.x;
    if (idx < 1024) { g_psum[idx] = 0.0; g_psq[idx] = 0.0; }
    for (int i = idx; i < BATCH*64*441; i += gridDim.x * 256) g_c1[i] = 0.0f;
}

// ---------------- stem conv: 7x7 s2 p3, NHWC in -> NCHW out --------------------
// tile = 16 oc x 16 out-rows x 32 cols; thread = 4 oc x 2 rows x 4 cols.
// ring-buffered input rows: 9 row-loads per c instead of 14 (crossbar relief).
__global__ __launch_bounds__(256, 2) void k_stem_conv(const float* __restrict__ x,
                                                      const float* __restrict__ w) {
    __shared__ float s_in[3*37*72];   // [c][37][72], 69 cols used
    __shared__ float s_w[2352];       // [(c*7+kh)*7+kw][16 oc]
    __shared__ float s_red[8][8];     // per-warp stats partials
    const int tid = threadIdx.x;
    const int b   = blockIdx.z >> 2;
    const int oc0 = (blockIdx.z & 3) * 16;
    const int base_ih = blockIdx.y * 32 - 3;
    const int base_iw = blockIdx.x * 64 - 3;

    for (int i = tid; i < 3*37*69; i += 256) {
        int c = i % 3, t = i / 3, ww = t % 69, hh = t / 69;
        int ih = base_ih + hh, iw = base_iw + ww;
        float v = 0.0f;
        if ((unsigned)ih < 512u && (unsigned)iw < 512u)
            v = x[((b*512 + ih)*512 + iw)*3 + c];
        s_in[(c*37 + hh)*72 + ww] = v;
    }
    for (int i = tid; i < 2352; i += 256) {
        int oc = i & 15, r = i >> 4;
        s_w[i] = w[(oc0 + oc)*147 + r];
    }
    __syncthreads();

    const int gx = tid & 7, gy = (tid >> 3) & 7, og = tid >> 6;
    // acc2[p][j][r]: oc pair (og*4+2p, +1), out col j, out row r (2gy+r)
    u64 acc2[2][4][2];
#pragma unroll
    for (int p = 0; p < 2; p++)
#pragma unroll
        for (int j = 0; j < 4; j++)
#pragma unroll
            for (int r = 0; r < 2; r++) acc2[p][j][r] = 0ull;

    float rb[4][13];   // ring of input rows (local row t = 4*gy + t)

#pragma unroll
    for (int c = 0; c < 3; c++) {
        const float* cin = &s_in[(c*37 + 4*gy)*72 + gx*8];
        // preload t = 0..3
#pragma unroll
        for (int t = 0; t < 4; t++) {
            const float* rp = cin + t*72;
            float4 a0 = *(const float4*)(rp);
            float4 a1 = *(const float4*)(rp + 4);
            float4 a2 = *(const float4*)(rp + 8);
            rb[t][0]=a0.x; rb[t][1]=a0.y; rb[t][2]=a0.z; rb[t][3]=a0.w;
            rb[t][4]=a1.x; rb[t][5]=a1.y; rb[t][6]=a1.z; rb[t][7]=a1.w;
            rb[t][8]=a2.x; rb[t][9]=a2.y; rb[t][10]=a2.z; rb[t][11]=a2.w;
            rb[t][12]=rp[12];
        }
#pragma unroll
        for (int kh = 0; kh < 7; kh++) {
            if (kh >= 2) {               // load t = kh+2 into slot (kh+2)&3
                const int t = kh + 2;
                const float* rp = cin + t*72;
                float* d = rb[t & 3];
                float4 a0 = *(const float4*)(rp);
                float4 a1 = *(const float4*)(rp + 4);
                float4 a2 = *(const float4*)(rp + 8);
                d[0]=a0.x; d[1]=a0.y; d[2]=a0.z; d[3]=a0.w;
                d[4]=a1.x; d[5]=a1.y; d[6]=a1.z; d[7]=a1.w;
                d[8]=a2.x; d[9]=a2.y; d[10]=a2.z; d[11]=a2.w;
                d[12]=rp[12];
            }
            const float* r0v = rb[kh & 3];        // row for out-row r=0 (t=kh)
            const float* r1v = rb[(kh + 2) & 3];  // row for out-row r=1 (t=kh+2)
            const float* wp = &s_w[((c*7 + kh)*7)*16 + og*4];
#pragma unroll
            for (int kw = 0; kw < 7; kw++) {
                float4 wv = *(const float4*)(wp + kw*16);
                u64 w01 = pack2(wv.x, wv.y);
                u64 w23 = pack2(wv.z, wv.w);
#pragma unroll
                for (int j = 0; j < 4; j++) {
                    float v0 = r0v[kw + 2*j];
                    u64 vv0 = pack2(v0, v0);
                    ffma2(acc2[0][j][0], w01, vv0);
                    ffma2(acc2[1][j][0], w23, vv0);
                    float v1 = r1v[kw + 2*j];
                    u64 vv1 = pack2(v1, v1);
                    ffma2(acc2[0][j][1], w01, vv1);
                    ffma2(acc2[1][j][1], w23, vv1);
                }
            }
        }
    }

    // unpack: accf[o][r][j]
    float accf[4][2][4];
#pragma unroll
    for (int p = 0; p < 2; p++)
#pragma unroll
        for (int j = 0; j < 4; j++)
#pragma unroll
            for (int r = 0; r < 2; r++) {
                float2 f2 = unpack2(acc2[p][j][r]);
                accf[2*p][r][j]   = f2.x;
                accf[2*p+1][r][j] = f2.y;
            }

    const int ow0 = blockIdx.x*32 + gx*4;
#pragma unroll
    for (int o = 0; o < 4; o++)
#pragma unroll
        for (int r = 0; r < 2; r++) {
            int oh = blockIdx.y*16 + 2*gy + r;
            int base = ((b*64 + oc0 + og*4 + o)*256 + oh)*256 + ow0;
            float4 st = make_float4(accf[o][r][0], accf[o][r][1],
                                    accf[o][r][2], accf[o][r][3]);
            *(float4*)&g_stem_out[base] = st;
        }

    // fused BN stats (4 oc, 8 values each)
    float red[8];
#pragma unroll
    for (int o = 0; o < 4; o++) {
        float s = 0.0f, q = 0.0f;
#pragma unroll
        for (int r = 0; r < 2; r++)
#pragma unroll
            for (int j = 0; j < 4; j++) {
                float v = accf[o][r][j];
                s += v; q = fmaf(v, v, q);
            }
        red[o] = s; red[4 + o] = q;
    }
#pragma unroll
    for (int off = 16; off; off >>= 1)
#pragma unroll
        for (int r = 0; r < 8; r++)
            red[r] += __shfl_down_sync(0xffffffffu, red[r], off);
    const int lane = tid & 31, wid = tid >> 5;
    if (lane == 0)
#pragma unroll
        for (int r = 0; r < 8; r++) s_red[wid][r] = red[r];
    __syncthreads();
    if (tid < 32) {
        int g2 = tid >> 3;
        int r  = tid & 7;
        float v = s_red[2*g2][r] + s_red[2*g2+1][r];
        int oc = oc0 + g2*4 + (r & 3);
        if (r < 4) atomicAdd(&g_psum[oc*16 + b], (double)v);
        else       atomicAdd(&g_psq [oc*16 + b], (double)v);
    }
}

__global__ void k_stem_prepare(const float* __restrict__ g,
                               const float* __restrict__ bb) {
    int c = threadIdx.x;
    double s = 0.0, q = 0.0;
    for (int b = 0; b < 16; b++) { s += g_psum[c*16 + b]; q += g_psq[c*16 + b]; }
    double N = 1048576.0;
    double mean = s / N;
    double var  = q / N - mean*mean;
    float sc = g[c] * rsqrtf((float)var + 1e-5f);
    g_sscale[c] = sc;
    g_sshift[c] = bb[c] - (float)mean * sc;
}

// ---------------- BN apply + relu + maxpool 3x3 s2 p1 -> f ---------------------
__global__ __launch_bounds__(256) void k_stem_pool() {
    const int idx = blockIdx.x*256 + threadIdx.x;   // 16 * 64 * 128 * 128
    const int px = idx & 127;
    const int py = (idx >> 7) & 127;
    const int z  = idx >> 14;                       // b*64 + c
    const float sc = g_sscale[z & 63], sh = g_sshift[z & 63];
    const float* p = g_stem_out + (size_t)z*65536;
    const int iy0 = 2*py - 1, ix0 = 2*px - 1;
    float m = 0.0f;
#pragma unroll
    for (int dr = 0; dr < 3; dr++) {
        int iy = iy0 + dr;
        if (iy < 0) continue;
        const float* row = p + iy*256;
#pragma unroll
        for (int dc = 0; dc < 3; dc++) {
            int ix = ix0 + dc;
            if (ix < 0) continue;
            float v = fmaf(row[ix], sc, sh);
            m = fmaxf(m, v);
        }
    }
    g_f[idx] = fmaxf(m, 0.0f);
}

// ---------------- on-the-fly grid_sample (±5° rotation) ------------------------
__device__ __forceinline__ float gs_tap(const float* p, float yy, float xx) {
    bool v = (xx >= 0.0f) && (xx < 128.0f) && (yy >= 0.0f) && (yy < 128.0f);
    int xi = (int)fminf(fmaxf(xx, 0.0f), 127.0f);
    int yi = (int)fminf(fmaxf(yy, 0.0f), 127.0f);
    return v ? p[yi*128 + xi] : 0.0f;
}

__device__ __forceinline__ float gs_eval(const float* __restrict__ p, int t,
                                         int yy, int xx) {
    const float C0 = 0.99619469809174553f;
    const float S5 = 0.08715574274765817f;
    float gx = (2*xx + 1)*(1.0f/128.0f) - 1.0f;
    float gy = (2*yy + 1)*(1.0f/128.0f) - 1.0f;
    float sg = t ? -S5 : S5;
    float gxp =  C0*gx + sg*gy;
    float gyp = -sg*gx + C0*gy;
    float ix = ((gxp + 1.0f)*128.0f - 1.0f)*0.5f;
    float iy = ((gyp + 1.0f)*128.0f - 1.0f)*0.5f;
    float x0f = floorf(ix), y0f = floorf(iy);
    float lx = ix - x0f, ly = iy - y0f;
    return gs_tap(p, y0f,        x0f)        * (1.0f - lx)*(1.0f - ly)
         + gs_tap(p, y0f + 1.0f, x0f)        * (1.0f - lx)*ly
         + gs_tap(p, y0f,        x0f + 1.0f) * lx*(1.0f - ly)
         + gs_tap(p, y0f + 1.0f, x0f + 1.0f) * lx*ly;
}

// ---------------- roialign -> h (16, 704, 23, 23) ------------------------------
__global__ void k_roialign(const float* __restrict__ box) {
    int idx = blockIdx.x*256 + threadIdx.x;
    if (idx >= 64*529) return;
    const int c  = idx / 529;
    const int sp = idx % 529;
    const int ph = sp / 23, pw = sp % 23;
    const int combo = blockIdx.y, b = blockIdx.z;

    const bool direct = (combo < 7);
    int slot, choff, t = 0;
    if (direct) { slot = combo; choff = combo*64; }
    else {
        int k2 = combo - 7;
        t = k2 >> 1;
        slot = k2 & 1; choff = 448 + k2*64;
    }
    const float* bp = box + b*28 + slot*4;
    float x1 = bp[0]*0.25f, y1 = bp[1]*0.25f;
    float x2 = bp[2]*0.25f, y2 = bp[3]*0.25f;
    float bw = fmaxf(x2 - x1, 1.0f) / 23.0f;
    float bh = fmaxf(y2 - y1, 1.0f) / 23.0f;
    const float* p = g_f + (size_t)(b*64 + c)*16384;

    float acc = 0.0f;
#pragma unroll
    for (int oi = 0; oi < 2; oi++)
#pragma unroll
    for (int oj = 0; oj < 2; oj++) {
        float py = (float)ph + (oi*0.5f + 0.25f);
        float px = (float)pw + (oj*0.5f + 0.25f);
        float yv = y1 + py*bh;
        float xv = x1 + px*bw;
        bool empty = (yv < -1.0f) || (yv > 128.0f) || (xv < -1.0f) || (xv > 128.0f);
        float yc = fminf(fmaxf(yv, 0.0f), 127.0f);
        float xc = fminf(fmaxf(xv, 0.0f), 127.0f);
        float y0f = floorf(yc), x0f = floorf(xc);
        int yi = (int)y0f, xi = (int)x0f;
        int yi1 = min(yi + 1, 127), xi1 = min(xi + 1, 127);
        float ly = yc - y0f, lx = xc - x0f;
        float hy = 1.0f - ly, hx = 1.0f - lx;
        float v;
        if (direct) {
            v = p[yi*128  + xi ] * hy*hx + p[yi*128  + xi1] * hy*lx
              + p[yi1*128 + xi ] * ly*hx + p[yi1*128 + xi1] * ly*lx;
        } else {
            v = gs_eval(p, t, yi,  xi ) * hy*hx + gs_eval(p, t, yi,  xi1) * hy*lx
              + gs_eval(p, t, yi1, xi ) * ly*hx + gs_eval(p, t, yi1, xi1) * ly*lx;
        }
        acc += empty ? 0.0f : v;
    }
    g_h[((size_t)(b*704 + choff + c))*529 + sp] = acc * 0.25f;
}

// ---------------- conv1: 3x3 p0, 704->64, 23x23 -> 21x21 -----------------------
__global__ __launch_bounds__(448) void k_conv1(const float* __restrict__ w) {
    __shared__ float s_in[4416];   // [8][23][24]
    __shared__ float s_w[576];     // [(c8*9+kh*3+kw)][8 oc]
    const int tid = threadIdx.x;
    const int split = blockIdx.x, ocg = blockIdx.y, b = blockIdx.z;
    const int oc0 = ocg*8;
    const int y = tid / 21, x = tid % 21;
    const bool act = tid < 441;
    u64 acc2[4];
#pragma unroll
    for (int o = 0; o < 4; o++) acc2[o] = 0ull;

    for (int cc = split*352; cc < split*352 + 352; cc += 8) {
        __syncthreads();
        for (int i = tid; i < 8*529; i += 448) {
            int c8 = i / 529, r = i % 529;
            s_in[(c8*23 + r/23)*24 + r%23] = g_h[((size_t)(b*704 + cc + c8))*529 + r];
        }
        for (int i = tid; i < 576; i += 448) {
            int oc = i & 7, r = i >> 3;
            s_w[i] = w[(oc0 + oc)*6336 + (cc + r/9)*9 + r%9];
        }
        __syncthreads();
        if (act) {
#pragma unroll
            for (int c8 = 0; c8 < 8; c8++) {
#pragma unroll
                for (int kh = 0; kh < 3; kh++) {
                    const float* rp = &s_in[(c8*23 + y + kh)*24 + x];
                    float v0 = rp[0], v1 = rp[1], v2 = rp[2];
                    const float* wp = &s_w[(c8*9 + kh*3)*8];
#pragma unroll
                    for (int kw = 0; kw < 3; kw++) {
                        float v = (kw == 0) ? v0 : (kw == 1) ? v1 : v2;
                        u64 vv = pack2(v, v);
                        float4 wa = *(const float4*)(wp + kw*8);
                        float4 wb = *(const float4*)(wp + kw*8 + 4);
                        u64 w0 = pack2(wa.x, wa.y);
                        u64 w1 = pack2(wa.z, wa.w);
                        u64 w2 = pack2(wb.x, wb.y);
                        u64 w3 = pack2(wb.z, wb.w);
                        ffma2(acc2[0], w0, vv);
                        ffma2(acc2[1], w1, vv);
                        ffma2(acc2[2], w2, vv);
                        ffma2(acc2[3], w3, vv);
                    }
                }
            }
        }
    }
    if (act) {
#pragma unroll
        for (int o = 0; o < 4; o++) {
            float2 f2 = unpack2(acc2[o]);
            atomicAdd(&g_c1[((size_t)(b*64 + oc0 + 2*o    ))*441 + tid], f2.x);
            atomicAdd(&g_c1[((size_t)(b*64 + oc0 + 2*o + 1))*441 + tid], f2.y);
        }
    }
}

// ---------------- bn1 stats --------------------------------------------------
__global__ void k_bn1stats(const float* __restrict__ g, const float* __restrict__ bb) {
    const int c = blockIdx.x;
    float s = 0.0f, q = 0.0f;
    for (int i = threadIdx.x; i < 7056; i += 256) {
        int b = i / 441, sp = i % 441;
        float v = g_c1[((size_t)(b*64 + c))*441 + sp];
        s += v; q += v*v;
    }
#pragma unroll
    for (int off = 16; off; off >>= 1) {
        s += __shfl_down_sync(0xffffffffu, s, off);
        q += __shfl_down_sync(0xffffffffu, q, off);
    }
    __shared__ float w1[8], w2[8];
    int lane = threadIdx.x & 31, wid = threadIdx.x >> 5;
    if (lane == 0) { w1[wid] = s; w2[wid] = q; }
    __syncthreads();
    if (threadIdx.x == 0) {
        float ts = 0.0f, tq = 0.0f;
        for (int i = 0; i < 8; i++) { ts += w1[i]; tq += w2[i]; }
        float mean = ts / 7056.0f;
        float var  = tq / 7056.0f - mean*mean;
        float sc = g[c] * rsqrtf(var + 1e-5f);
        g_b1scale[c] = sc;
        g_b1shift[c] = bb[c] - mean*sc;
    }
}

// ---------------- bn1 apply + relu + maxpool 2x2 s2 ----------------------------
__global__ void k_pool2() {
    int idx = blockIdx.x*256 + threadIdx.x;
    if (idx >= BATCH*64*100) return;
    int b = idx / 6400, r = idx % 6400;
    int c = r / 100, sxy = r % 100;
    int y = sxy / 10, x = sxy % 10;
    float sc = g_b1scale[c], sh = g_b1shift[c];
    const float* p = g_c1 + (size_t)(b*64 + c)*441;
    float m = -1e30f;
#pragma unroll
    for (int dr = 0; dr < 2; dr++)
#pragma unroll
        for (int dc = 0; dc < 2; dc++) {
            float v = fmaxf(fmaf(p[(2*y + dr)*21 + 2*x + dc], sc, sh), 0.0f);
            m = fmaxf(m, v);
        }
    g_p1[idx] = m;
}

// ---------------- conv2: 3x3 p0, 64->32, 10x10 -> 8x8, +bias, relu ------------
__global__ void k_conv2(const float* __restrict__ w, const float* __restrict__ bias) {
    __shared__ float s_in[3200];   // [32][10][10]
    __shared__ float s_w[2304];    // [(c*9+t)][8 oc]
    const int tid = threadIdx.x;
    const int ocg = blockIdx.x, b = blockIdx.y;
    const int oc0 = ocg*8;
    const int s = tid & 63, og = tid >> 6;
    const int y = s >> 3, x = s & 7;
    float acc[2] = {0.0f, 0.0f};

    for (int cc = 0; cc < 64; cc += 32) {
        __syncthreads();
        for (int i = tid; i < 3200; i += 256)
            s_in[i] = g_p1[((size_t)(b*64 + cc))*100 + i];
        for (int i = tid; i < 2304; i += 256) {
            int oc = i & 7, r = i >> 3;
            s_w[i] = w[(oc0 + oc)*576 + (cc + r/9)*9 + r%9];
        }
        __syncthreads();
#pragma unroll 4
        for (int c = 0; c < 32; c++) {
#pragma unroll
            for (int kh = 0; kh < 3; kh++) {
                const float* rp = &s_in[(c*10 + y + kh)*10 + x];
                float v0 = rp[0], v1 = rp[1], v2 = rp[2];
                const float* wp = &s_w[(c*9 + kh*3)*8 + og*2];
                acc[0] = fmaf(wp[0],  v0, acc[0]); acc[1] = fmaf(wp[1],  v0, acc[1]);
                acc[0] = fmaf(wp[8],  v1, acc[0]); acc[1] = fmaf(wp[9],  v1, acc[1]);
                acc[0] = fmaf(wp[16], v2, acc[0]); acc[1] = fmaf(wp[17], v2, acc[1]);
            }
        }
    }
#pragma unroll
    for (int o = 0; o < 2; o++) {
        int oc = oc0 + og*2 + o;
        g_fcin[b*2048 + oc*64 + s] = fmaxf(acc[o] + bias[oc], 0.0f);
    }
}

// ---------------- fc1: (16,2048) x (128,2048)^T + b, relu ----------------------
__global__ void k_fc1(const float* __restrict__ w, const float* __restrict__ bias) {
    const int j = blockIdx.x;
    float acc[16];
#pragma unroll
    for (int b = 0; b < 16; b++) acc[b] = 0.0f;
    for (int k = threadIdx.x; k < 2048; k += 256) {
        float wv = w[j*2048 + k];
#pragma unroll
        for (int b = 0; b < 16; b++)
            acc[b] = fmaf(wv, g_fcin[b*2048 + k], acc[b]);
    }
#pragma unroll
    for (int off = 16; off; off >>= 1)
#pragma unroll
        for (int b = 0; b < 16; b++)
            acc[b] += __shfl_down_sync(0xffffffffu, acc[b], off);
    __shared__ float red[8][16];
    int lane = threadIdx.x & 31, wid = threadIdx.x >> 5;
    if (lane == 0)
#pragma unroll
        for (int b = 0; b < 16; b++) red[wid][b] = acc[b];
    __syncthreads();
    if (threadIdx.x < 16) {
        float sv = 0.0f;
        for (int wdx = 0; wdx < 8; wdx++) sv += red[wdx][threadIdx.x];
        g_fc1v[threadIdx.x*128 + j] = fmaxf(sv + bias[j], 0.0f);
    }
}

// ---------------- head + tanh --------------------------------------------------
__global__ void k_head(const float* __restrict__ w, const float* __restrict__ bias,
                       float* __restrict__ out) {
    int t = threadIdx.x;          // 192 threads
    int b = t / 12, j = t % 12;
    float s = bias[j];
    for (int k = 0; k < 128; k++)
        s = fmaf(g_fc1v[b*128 + k], w[j*128 + k], s);
    out[t] = tanhf(s);
}

// ---------------- launch -------------------------------------------------------
extern "C" void kernel_launch(void* const* d_in, const int* in_sizes, int n_in,
                              void* d_out, int out_size) {
    const float* x       = (const float*)d_in[0];
    const float* box     = (const float*)d_in[1];
    const float* stem_w  = (const float*)d_in[2];
    const float* stem_g  = (const float*)d_in[3];
    const float* stem_b  = (const float*)d_in[4];
    const float* conv1_w = (const float*)d_in[5];
    /* conv1_b (d_in[6]) cancels exactly inside batchnorm — unused */
    const float* bn1_g   = (const float*)d_in[7];
    const float* bn1_b   = (const float*)d_in[8];
    const float* conv2_w = (const float*)d_in[9];
    const float* conv2_b = (const float*)d_in[10];
    const float* fc1_w   = (const float*)d_in[11];
    const float* fc1_b   = (const float*)d_in[12];
    const float* head_w  = (const float*)d_in[13];
    const float* head_b  = (const float*)d_in[14];
    float* out = (float*)d_out;

    k_zero<<<512, 256>>>();
    k_stem_conv<<<dim3(8, 16, 64), 256>>>(x, stem_w);
    k_stem_prepare<<<1, 64>>>(stem_g, stem_b);
    k_stem_pool<<<65536, 256>>>();
    k_roialign<<<dim3(133, 11, 16), 256>>>(box);
    k_conv1<<<dim3(2, 8, 16), 448>>>(conv1_w);
    k_bn1stats<<<64, 256>>>(bn1_g, bn1_b);
    k_pool2<<<400, 256>>>();
    k_conv2<<<dim3(4, 16), 256>>>(conv2_w, conv2_b);
    k_fc1<<<128, 256>>>(fc1_w, fc1_b);
    k_head<<<1, 192>>>(head_w, head_b, out);
}